// round 13
// baseline (speedup 1.0000x reference)
#include <cuda_runtime.h>
#include <math.h>

#define N_ENT 200000
#define N_USR 100000
#define D     64
#define NEDGE 1500000
#define NINT  1000000
#define NVIRT 3
#define NRELM1 10
#define NBKT  (NVIRT * N_ENT)
#define NBKT_ALL (NBKT + N_USR)          // joint bucket space (entity then user)
#define NVAL_ALL (NEDGE + NINT)          // joint CSR value space
#define EPSV  1e-12f
#define SCAN_B 1024
#define TPB   256
#define RBLK  ((N_ENT / 4) * 32 / TPB)   // 6250 entity blocks (4 rows/warp)
#define UBLK  ((N_USR / 4) * 32 / TPB)   // 3125 user blocks

// ---------------- scratch (static device globals; zero-initialized) ----------
__device__ float g_entB[(size_t)N_ENT * D];
__device__ float g_entC[(size_t)N_ENT * D];
__device__ float g_usrB[(size_t)N_USR * D];
__device__ float g_usrC[(size_t)N_USR * D];
__device__ int   g_csr[NVAL_ALL];        // entity tails then user items (joint)
__device__ int   g_cnt[NBKT_ALL];        // joint counts   (zeroed by tail of last hop)
__device__ int   g_off[NBKT_ALL + 1];    // joint exclusive-scan offsets
__device__ int   g_cur[NBKT_ALL];        // scatter cursors (zeroed by tail of last hop)
__device__ int   g_bsum[2048];
__device__ float g_w[2 * 3];             // softmaxed agg weights per hop

// ---------------- fused count: inline remap, entities + users, + softmax -----
__global__ void k_count(const int* __restrict__ head, const int* __restrict__ etype,
                        const int* __restrict__ uidx,
                        const float* __restrict__ latent, const float* __restrict__ relw,
                        const float* __restrict__ aggw) {
    __shared__ int srm[NRELM1];
    if (threadIdx.x < NRELM1) {
        int t = threadIdx.x;
        float best = -1e30f; int bi = 0;
        for (int v = 0; v < NVIRT; v++) {
            float s = 0.f;
            for (int d = 0; d < D; d++) s += relw[t * D + d] * latent[v * D + d];
            if (s > best) { best = s; bi = v; }
        }
        srm[t] = bi;
    }
    if (blockIdx.x == 0 && threadIdx.x >= 32 && threadIdx.x < 34) {
        int h = threadIdx.x - 32;
        float a0 = aggw[h * 3 + 0], a1 = aggw[h * 3 + 1], a2 = aggw[h * 3 + 2];
        float m = fmaxf(a0, fmaxf(a1, a2));
        float e0 = expf(a0 - m), e1 = expf(a1 - m), e2 = expf(a2 - m);
        float s = e0 + e1 + e2;
        g_w[h * 3 + 0] = e0 / s; g_w[h * 3 + 1] = e1 / s; g_w[h * 3 + 2] = e2 / s;
    }
    __syncthreads();
    int gid = blockIdx.x * blockDim.x + threadIdx.x;
    if (gid < NEDGE) {
        atomicAdd(&g_cnt[srm[etype[gid] - 1] * N_ENT + head[gid]], 1);
    } else if (gid < NVAL_ALL) {
        atomicAdd(&g_cnt[NBKT + uidx[gid - NEDGE]], 1);
    }
}

// ---------------- 3-kernel scan (measured cheap) ------------------------------
__global__ void k_scan1(const int* __restrict__ in, int* __restrict__ out,
                        int* __restrict__ bsum, int n) {
    __shared__ int sh[SCAN_B];
    int i = blockIdx.x * SCAN_B + threadIdx.x;
    int v = (i < n) ? in[i] : 0;
    sh[threadIdx.x] = v; __syncthreads();
    for (int o = 1; o < SCAN_B; o <<= 1) {
        int t = (threadIdx.x >= o) ? sh[threadIdx.x - o] : 0;
        __syncthreads();
        sh[threadIdx.x] += t;
        __syncthreads();
    }
    if (i < n) out[i] = sh[threadIdx.x] - v;
    if (threadIdx.x == SCAN_B - 1) bsum[blockIdx.x] = sh[threadIdx.x];
}
__global__ void k_scan2(int* __restrict__ bsum, int nb) {
    __shared__ int sh[SCAN_B];
    int v = (threadIdx.x < nb) ? bsum[threadIdx.x] : 0;
    sh[threadIdx.x] = v; __syncthreads();
    for (int o = 1; o < SCAN_B; o <<= 1) {
        int t = (threadIdx.x >= o) ? sh[threadIdx.x - o] : 0;
        __syncthreads();
        sh[threadIdx.x] += t;
        __syncthreads();
    }
    if (threadIdx.x < nb) bsum[threadIdx.x] = sh[threadIdx.x] - v;
}
__global__ void k_scan3(int* __restrict__ out, const int* __restrict__ bsum, int n) {
    int i = blockIdx.x * SCAN_B + threadIdx.x;
    if (i < n) out[i] += bsum[blockIdx.x];
}

// ---------------- fused scatter ------------------------------------------------
__global__ void k_scatter(const int* __restrict__ head, const int* __restrict__ tail,
                          const int* __restrict__ etype,
                          const int* __restrict__ uidx, const int* __restrict__ iidx,
                          const float* __restrict__ latent, const float* __restrict__ relw) {
    __shared__ int srm[NRELM1];
    if (threadIdx.x < NRELM1) {
        int t = threadIdx.x;
        float best = -1e30f; int bi = 0;
        for (int v = 0; v < NVIRT; v++) {
            float s = 0.f;
            for (int d = 0; d < D; d++) s += relw[t * D + d] * latent[v * D + d];
            if (s > best) { best = s; bi = v; }
        }
        srm[t] = bi;
    }
    __syncthreads();
    int gid = blockIdx.x * blockDim.x + threadIdx.x;
    if (gid < NEDGE) {
        int b = srm[etype[gid] - 1] * N_ENT + head[gid];
        int pos = g_off[b] + atomicAdd(&g_cur[b], 1);
        g_csr[pos] = tail[gid];
    } else if (gid < NVAL_ALL) {
        int j = gid - NEDGE;
        int b = NBKT + uidx[j];
        int pos = g_off[b] + atomicAdd(&g_cur[b], 1);
        g_csr[pos] = iidx[j];
    }
}

// ---------------- 8-lane helpers (8 lanes per row, lane = 8 dims) -------------
__device__ __forceinline__ float dot8(float4 a0, float4 a1, float4 b0, float4 b1,
                                      unsigned mask) {
    float p = a0.x * b0.x + a0.y * b0.y + a0.z * b0.z + a0.w * b0.w
            + a1.x * b1.x + a1.y * b1.y + a1.z * b1.z + a1.w * b1.w;
    p += __shfl_xor_sync(mask, p, 4);
    p += __shfl_xor_sync(mask, p, 2);
    p += __shfl_xor_sync(mask, p, 1);
    return p;
}

// ---------------- fused hop: entity blocks [0,RBLK), user blocks [RBLK,RBLK+UBLK)
__global__ void __launch_bounds__(TPB) k_hop(const float* __restrict__ ent,
                                             float* __restrict__ ent_out,
                                             const float* __restrict__ usr,
                                             float* __restrict__ usr_out,
                                             float* __restrict__ out, int hop) {
    int q = (threadIdx.x >> 3) & 3;
    int l8 = threadIdx.x & 7;
    unsigned mask = 0xFFu << (q * 8);

    if (blockIdx.x < RBLK) {
        // ===== entity path: 4 rows per warp =====
        int gw = (blockIdx.x * TPB + threadIdx.x) >> 5;
        int n = gw * 4 + q;
        const float* ep = ent + (size_t)n * D + l8 * 8;
        float4 e0 = *(const float4*)ep;
        float4 e1 = *(const float4*)(ep + 4);
        float4 g0, g1; g0.x = g0.y = g0.z = g0.w = 0.f; g1 = g0;

        #pragma unroll
        for (int i = 0; i < NVIRT; i++) {
            int r = i * N_ENT + n;
            int beg = g_off[r];
            int deg = g_off[r + 1] - beg;
            float inv = 1.0f / fmaxf((float)deg, 1.0f);
            // iter 0: mean
            float4 a0, a1; a0.x = a0.y = a0.z = a0.w = 0.f; a1 = a0;
            for (int j = 0; j < deg; j++) {
                const float* xp = ent + (size_t)g_csr[beg + j] * D + l8 * 8;
                float4 x0 = *(const float4*)xp;
                float4 x1 = *(const float4*)(xp + 4);
                a0.x += x0.x; a0.y += x0.y; a0.z += x0.z; a0.w += x0.w;
                a1.x += x1.x; a1.y += x1.y; a1.z += x1.z; a1.w += x1.w;
            }
            float4 m0, m1;
            m0.x = a0.x * inv; m0.y = a0.y * inv; m0.z = a0.z * inv; m0.w = a0.w * inv;
            m1.x = a1.x * inv; m1.y = a1.y * inv; m1.z = a1.z * inv; m1.w = a1.w * inv;
            float sq = dot8(m0, m1, m0, m1, mask);
            float f = (sq / (sq + 1.0f)) / fmaxf(sqrtf(sq), EPSV);
            float4 u10, u11;
            u10.x = m0.x * f + e0.x; u10.y = m0.y * f + e0.y;
            u10.z = m0.z * f + e0.z; u10.w = m0.w * f + e0.w;
            u11.x = m1.x * f + e1.x; u11.y = m1.y * f + e1.y;
            u11.z = m1.z * f + e1.z; u11.w = m1.w * f + e1.w;
            // iter 1: coef = dot(u1,x)
            a0.x = a0.y = a0.z = a0.w = 0.f; a1 = a0;
            for (int j = 0; j < deg; j++) {
                const float* xp = ent + (size_t)g_csr[beg + j] * D + l8 * 8;
                float4 x0 = *(const float4*)xp;
                float4 x1 = *(const float4*)(xp + 4);
                float p = dot8(u10, u11, x0, x1, mask);
                a0.x += p * x0.x; a0.y += p * x0.y; a0.z += p * x0.z; a0.w += p * x0.w;
                a1.x += p * x1.x; a1.y += p * x1.y; a1.z += p * x1.z; a1.w += p * x1.w;
            }
            m0.x = a0.x * inv; m0.y = a0.y * inv; m0.z = a0.z * inv; m0.w = a0.w * inv;
            m1.x = a1.x * inv; m1.y = a1.y * inv; m1.z = a1.z * inv; m1.w = a1.w * inv;
            sq = dot8(m0, m1, m0, m1, mask);
            f = (sq / (sq + 1.0f)) / fmaxf(sqrtf(sq), EPSV);
            float4 u20, u21;
            u20.x = m0.x * f + e0.x; u20.y = m0.y * f + e0.y;
            u20.z = m0.z * f + e0.z; u20.w = m0.w * f + e0.w;
            u21.x = m1.x * f + e1.x; u21.y = m1.y * f + e1.y;
            u21.z = m1.z * f + e1.z; u21.w = m1.w * f + e1.w;
            // iter 2: coef = dot(u1,x)^2 * dot(u2,x); no squash
            a0.x = a0.y = a0.z = a0.w = 0.f; a1 = a0;
            for (int j = 0; j < deg; j++) {
                const float* xp = ent + (size_t)g_csr[beg + j] * D + l8 * 8;
                float4 x0 = *(const float4*)xp;
                float4 x1 = *(const float4*)(xp + 4);
                float p1 = dot8(u10, u11, x0, x1, mask);
                float p2 = dot8(u20, u21, x0, x1, mask);
                float c = p1 * p1 * p2;
                a0.x += c * x0.x; a0.y += c * x0.y; a0.z += c * x0.z; a0.w += c * x0.w;
                a1.x += c * x1.x; a1.y += c * x1.y; a1.z += c * x1.z; a1.w += c * x1.w;
            }
            float wv = g_w[hop * 3 + i];
            g0.x += wv * (a0.x * inv + e0.x); g0.y += wv * (a0.y * inv + e0.y);
            g0.z += wv * (a0.z * inv + e0.z); g0.w += wv * (a0.w * inv + e0.w);
            g1.x += wv * (a1.x * inv + e1.x); g1.y += wv * (a1.y * inv + e1.y);
            g1.z += wv * (a1.z * inv + e1.z); g1.w += wv * (a1.w * inv + e1.w);
        }

        float sq = dot8(g0, g1, g0, g1, mask);
        float f = 1.0f / fmaxf(sqrtf(sq), EPSV);
        float4 o0, o1;
        o0.x = g0.x * f; o0.y = g0.y * f; o0.z = g0.z * f; o0.w = g0.w * f;
        o1.x = g1.x * f; o1.y = g1.y * f; o1.z = g1.z * f; o1.w = g1.w * f;
        float* wp = ent_out + (size_t)n * D + l8 * 8;
        *(float4*)wp = o0; *(float4*)(wp + 4) = o1;
        float* op = out + (size_t)n * D + l8 * 8;
        if (hop == 0) {               // out = orig ent + o (ent IS orig on hop 0)
            float4 v0, v1;
            v0.x = e0.x + o0.x; v0.y = e0.y + o0.y; v0.z = e0.z + o0.z; v0.w = e0.w + o0.w;
            v1.x = e1.x + o1.x; v1.y = e1.y + o1.y; v1.z = e1.z + o1.z; v1.w = e1.w + o1.w;
            *(float4*)op = v0; *(float4*)(op + 4) = v1;
        } else {
            float4 p0 = *(float4*)op, p1 = *(float4*)(op + 4);
            p0.x += o0.x; p0.y += o0.y; p0.z += o0.z; p0.w += o0.w;
            p1.x += o1.x; p1.y += o1.y; p1.z += o1.z; p1.w += o1.w;
            *(float4*)op = p0; *(float4*)(op + 4) = p1;
        }
    } else {
        // ===== user path: 4 users per warp =====
        int gtid_u = (blockIdx.x - RBLK) * TPB + threadIdx.x;
        // tail-of-pipeline zeroing of CSR-build state for the NEXT replay
        if (hop == 1 && gtid_u < NBKT_ALL) { g_cnt[gtid_u] = 0; g_cur[gtid_u] = 0; }
        int gw = gtid_u >> 5;
        int n = gw * 4 + q;
        float* out_usr = out + (size_t)N_ENT * D;
        int beg = g_off[NBKT + n];
        int deg = g_off[NBKT + n + 1] - beg;
        float inv = 1.0f / fmaxf((float)deg, 1.0f);
        const float* up = usr + (size_t)n * D + l8 * 8;
        float4 e0 = *(const float4*)up;
        float4 e1 = *(const float4*)(up + 4);

        // iter 0
        float4 a0, a1; a0.x = a0.y = a0.z = a0.w = 0.f; a1 = a0;
        for (int j = 0; j < deg; j++) {
            const float* xp = ent + (size_t)g_csr[beg + j] * D + l8 * 8;
            float4 x0 = *(const float4*)xp;
            float4 x1 = *(const float4*)(xp + 4);
            a0.x += x0.x; a0.y += x0.y; a0.z += x0.z; a0.w += x0.w;
            a1.x += x1.x; a1.y += x1.y; a1.z += x1.z; a1.w += x1.w;
        }
        float4 m0, m1;
        m0.x = a0.x * inv; m0.y = a0.y * inv; m0.z = a0.z * inv; m0.w = a0.w * inv;
        m1.x = a1.x * inv; m1.y = a1.y * inv; m1.z = a1.z * inv; m1.w = a1.w * inv;
        float sq = dot8(m0, m1, m0, m1, mask);
        float f = (sq / (sq + 1.0f)) / fmaxf(sqrtf(sq), EPSV);
        float4 u0, u1;
        u0.x = m0.x * f + e0.x; u0.y = m0.y * f + e0.y;
        u0.z = m0.z * f + e0.z; u0.w = m0.w * f + e0.w;
        u1.x = m1.x * f + e1.x; u1.y = m1.y * f + e1.y;
        u1.z = m1.z * f + e1.z; u1.w = m1.w * f + e1.w;

        // iter 1
        a0.x = a0.y = a0.z = a0.w = 0.f; a1 = a0;
        for (int j = 0; j < deg; j++) {
            const float* xp = ent + (size_t)g_csr[beg + j] * D + l8 * 8;
            float4 x0 = *(const float4*)xp;
            float4 x1 = *(const float4*)(xp + 4);
            float p = dot8(u0, u1, x0, x1, mask);
            a0.x += p * x0.x; a0.y += p * x0.y; a0.z += p * x0.z; a0.w += p * x0.w;
            a1.x += p * x1.x; a1.y += p * x1.y; a1.z += p * x1.z; a1.w += p * x1.w;
        }
        m0.x = a0.x * inv; m0.y = a0.y * inv; m0.z = a0.z * inv; m0.w = a0.w * inv;
        m1.x = a1.x * inv; m1.y = a1.y * inv; m1.z = a1.z * inv; m1.w = a1.w * inv;
        sq = dot8(m0, m1, m0, m1, mask);
        f = (sq / (sq + 1.0f)) / fmaxf(sqrtf(sq), EPSV);
        u0.x = m0.x * f + e0.x; u0.y = m0.y * f + e0.y;
        u0.z = m0.z * f + e0.z; u0.w = m0.w * f + e0.w;
        u1.x = m1.x * f + e1.x; u1.y = m1.y * f + e1.y;
        u1.z = m1.z * f + e1.z; u1.w = m1.w * f + e1.w;

        // iter 2 + l2norm + residual
        a0.x = a0.y = a0.z = a0.w = 0.f; a1 = a0;
        for (int j = 0; j < deg; j++) {
            const float* xp = ent + (size_t)g_csr[beg + j] * D + l8 * 8;
            float4 x0 = *(const float4*)xp;
            float4 x1 = *(const float4*)(xp + 4);
            float p = dot8(u0, u1, x0, x1, mask);
            a0.x += p * x0.x; a0.y += p * x0.y; a0.z += p * x0.z; a0.w += p * x0.w;
            a1.x += p * x1.x; a1.y += p * x1.y; a1.z += p * x1.z; a1.w += p * x1.w;
        }
        float4 v0, v1;
        v0.x = a0.x * inv + e0.x; v0.y = a0.y * inv + e0.y;
        v0.z = a0.z * inv + e0.z; v0.w = a0.w * inv + e0.w;
        v1.x = a1.x * inv + e1.x; v1.y = a1.y * inv + e1.y;
        v1.z = a1.z * inv + e1.z; v1.w = a1.w * inv + e1.w;
        sq = dot8(v0, v1, v0, v1, mask);
        f = 1.0f / fmaxf(sqrtf(sq), EPSV);
        float4 o0, o1;
        o0.x = v0.x * f; o0.y = v0.y * f; o0.z = v0.z * f; o0.w = v0.w * f;
        o1.x = v1.x * f; o1.y = v1.y * f; o1.z = v1.z * f; o1.w = v1.w * f;
        float* wp = usr_out + (size_t)n * D + l8 * 8;
        *(float4*)wp = o0; *(float4*)(wp + 4) = o1;
        float* op = out_usr + (size_t)n * D + l8 * 8;
        if (hop == 0) {
            float4 w0, w1;
            w0.x = e0.x + o0.x; w0.y = e0.y + o0.y; w0.z = e0.z + o0.z; w0.w = e0.w + o0.w;
            w1.x = e1.x + o1.x; w1.y = e1.y + o1.y; w1.z = e1.z + o1.z; w1.w = e1.w + o1.w;
            *(float4*)op = w0; *(float4*)(op + 4) = w1;
        } else {
            float4 p0 = *(float4*)op, p1 = *(float4*)(op + 4);
            p0.x += o0.x; p0.y += o0.y; p0.z += o0.z; p0.w += o0.w;
            p1.x += o1.x; p1.y += o1.y; p1.z += o1.z; p1.w += o1.w;
            *(float4*)op = p0; *(float4*)(op + 4) = p1;
        }
    }
}

// ---------------- host orchestration ------------------------------------------
extern "C" void kernel_launch(void* const* d_in, const int* in_sizes, int n_in,
                              void* d_out, int out_size) {
    (void)in_sizes; (void)n_in; (void)out_size;
    const float* entity_emb = (const float*)d_in[0];
    const float* user_emb   = (const float*)d_in[1];
    const float* latent     = (const float*)d_in[2];
    const float* relw       = (const float*)d_in[3];
    const float* aggw       = (const float*)d_in[4];
    const int*   eidx       = (const int*)d_in[5];
    const int*   etype      = (const int*)d_in[6];
    const int*   uidx       = (const int*)d_in[7];
    const int*   iidx       = (const int*)d_in[8];
    float* out = (float*)d_out;
    const int* head = eidx;
    const int* tail = eidx + NEDGE;

    void *p_cnt, *p_off, *p_bsum, *p_entB, *p_entC, *p_usrB, *p_usrC;
    cudaGetSymbolAddress(&p_cnt,  g_cnt);
    cudaGetSymbolAddress(&p_off,  g_off);
    cudaGetSymbolAddress(&p_bsum, g_bsum);
    cudaGetSymbolAddress(&p_entB, g_entB);
    cudaGetSymbolAddress(&p_entC, g_entC);
    cudaGetSymbolAddress(&p_usrB, g_usrB);
    cudaGetSymbolAddress(&p_usrC, g_usrC);

    const int CB  = (NVAL_ALL + TPB - 1) / TPB;
    const int NB  = (NBKT_ALL + SCAN_B - 1) / SCAN_B;   // 684

    // 5-kernel prologue (counters pre-zeroed by previous replay's tail / static init)
    k_count<<<CB, TPB>>>(head, etype, uidx, latent, relw, aggw);
    k_scan1<<<NB, SCAN_B>>>((const int*)p_cnt, (int*)p_off, (int*)p_bsum, NBKT_ALL);
    k_scan2<<<1, SCAN_B>>>((int*)p_bsum, NB);
    k_scan3<<<NB, SCAN_B>>>((int*)p_off, (const int*)p_bsum, NBKT_ALL);
    k_scatter<<<CB, TPB>>>(head, tail, etype, uidx, iidx, latent, relw);

    // hop 0 (reads original embeddings directly); entity + user concurrent
    k_hop<<<RBLK + UBLK, TPB>>>(entity_emb, (float*)p_entB,
                                user_emb, (float*)p_usrB, out, 0);
    // hop 1 (user path zeroes CSR-build state for next replay)
    k_hop<<<RBLK + UBLK, TPB>>>((const float*)p_entB, (float*)p_entC,
                                (const float*)p_usrB, (float*)p_usrC, out, 1);
}